// round 6
// baseline (speedup 1.0000x reference)
#include <cuda_runtime.h>
#include <cuda_bf16.h>
#include <stdint.h>
#include <math.h>

#define NHALF 2048
#define NTOT  4096
#define DDIM  512

#define BM 128
#define BN 128
#define BK 64
#define NCHUNK (DDIM / BK)   // 8
#define NTILE 32
#define NBLK 528             // upper-triangle tiles

#define TPADB 80                     // bytes per smem tile row (64B data + pad)
#define TILE_B (128 * TPADB)         // 10240 B per tile
#define STAGE_B (4 * TILE_B)         // q1A, q2A, q1B, q2B
#define SM_TOTAL (2 * STAGE_B)       // 81920 B (dist tile overlays this)
#define DPAD 133                     // fp32 dist tile row stride

// ---------------- device globals ----------------
__device__ float        g_sq[NTOT];
__device__ unsigned     g_negmin_bits[NTOT];
__device__ float        g_pos[NTOT];
__device__ signed char  g_q1[NTOT * DDIM];
__device__ signed char  g_q2[NTOT * DDIM];

// ---------------- helpers ----------------
__device__ __forceinline__ uint32_t smem_u32(const void* p) {
    uint32_t a;
    asm("{ .reg .u64 t; cvta.to.shared.u64 t, %1; cvt.u32.u64 %0, t; }"
        : "=r"(a) : "l"(p));
    return a;
}
__device__ __forceinline__ void cp16(uint32_t dst, const void* src) {
    asm volatile("cp.async.cg.shared.global [%0], [%1], 16;"
                 :: "r"(dst), "l"(src));
}
#define CP_COMMIT() asm volatile("cp.async.commit_group;" ::: "memory")
#define CP_WAIT1()  asm volatile("cp.async.wait_group 1;" ::: "memory")
#define CP_WAIT0()  asm volatile("cp.async.wait_group 0;" ::: "memory")

__device__ __forceinline__ void ldx4(uint32_t* r, uint32_t addr) {
    asm volatile("ldmatrix.sync.aligned.m8n8.x4.shared.b16 {%0,%1,%2,%3}, [%4];"
                 : "=r"(r[0]), "=r"(r[1]), "=r"(r[2]), "=r"(r[3]) : "r"(addr));
}
__device__ __forceinline__ void imma16832(int* d, const uint32_t* a,
                                          const uint32_t* b) {
    asm volatile(
        "mma.sync.aligned.m16n8k32.row.col.s32.s8.s8.s32 "
        "{%0,%1,%2,%3}, {%4,%5,%6,%7}, {%8,%9}, {%0,%1,%2,%3};"
        : "+r"(d[0]), "+r"(d[1]), "+r"(d[2]), "+r"(d[3])
        : "r"(a[0]), "r"(a[1]), "r"(a[2]), "r"(a[3]), "r"(b[0]), "r"(b[1]));
}

// ---------------------------------------------------------------------------
// Kernel 1: row sums of squares + int8 two-digit quantization + scratch reset
// ---------------------------------------------------------------------------
__global__ void prep_kernel(const float* __restrict__ h1,
                            const float* __restrict__ h2) {
    int r = blockIdx.x;
    const float* src = (r < NHALF) ? (h1 + (size_t)r * DDIM)
                                   : (h2 + (size_t)(r - NHALF) * DDIM);
    int t = threadIdx.x;  // 0..127
    float4 v = ((const float4*)src)[t];
    float s = v.x * v.x + v.y * v.y + v.z * v.z + v.w * v.w;

    float xs[4] = {v.x, v.y, v.z, v.w};
    signed char q1c[4], q2c[4];
    #pragma unroll
    for (int i = 0; i < 4; i++) {
        int q1 = __float2int_rn(xs[i] * 16.0f);
        q1 = max(-127, min(127, q1));
        float rres = xs[i] - (float)q1 * 0.0625f;
        int q2 = __float2int_rn(rres * 4096.0f);
        q2 = max(-127, min(127, q2));
        q1c[i] = (signed char)q1;
        q2c[i] = (signed char)q2;
    }
    size_t base = (size_t)r * DDIM + 4 * t;
    *(char4*)(g_q1 + base) = make_char4(q1c[0], q1c[1], q1c[2], q1c[3]);
    *(char4*)(g_q2 + base) = make_char4(q2c[0], q2c[1], q2c[2], q2c[3]);

    #pragma unroll
    for (int off = 16; off > 0; off >>= 1)
        s += __shfl_xor_sync(0xffffffffu, s, off);

    __shared__ float warp_s[4];
    int lane = t & 31, wid = t >> 5;
    if (lane == 0) warp_s[wid] = s;
    __syncthreads();
    if (t == 0) {
        g_sq[r] = warp_s[0] + warp_s[1] + warp_s[2] + warp_s[3];
        g_negmin_bits[r] = 0x7f800000u;  // +inf
        g_pos[r] = 0.0f;
    }
}

// ---------------------------------------------------------------------------
// async-load one pipeline stage (4 tiles of 128 x 64 int8)
// ---------------------------------------------------------------------------
__device__ __forceinline__ void load_stage(uint32_t smb, int stage,
                                           const signed char* a1,
                                           const signed char* a2,
                                           const signed char* b1,
                                           const signed char* b2,
                                           int k0, int tid) {
    const signed char* srcs[4] = {a1, a2, b1, b2};
    uint32_t base = smb + stage * STAGE_B;
    #pragma unroll
    for (int t = 0; t < 4; t++) {
        #pragma unroll
        for (int i = 0; i < 2; i++) {
            int chunk = tid * 2 + i;       // 0..511
            int r = chunk >> 2;            // 0..127
            int c = chunk & 3;             // 16B chunk within 64B row
            cp16(base + t * TILE_B + r * TPADB + c * 16,
                 srcs[t] + (size_t)r * DDIM + k0 + c * 16);
        }
    }
}

// ---------------------------------------------------------------------------
// Kernel 2: int8 two-digit IMMA X*X^T (upper triangle) + distance epilogue
// ---------------------------------------------------------------------------
__global__ __launch_bounds__(256, 1)
void gemm_dist_kernel() {
    extern __shared__ char smem[];
    const uint32_t smb = smem_u32(smem);
    const int tid = threadIdx.x;
    const int wid = tid >> 5, lane = tid & 31;

    // decode upper-triangle tile index
    int t = blockIdx.x;
    int bi = 0;
    while (t >= NTILE - bi) { t -= NTILE - bi; bi++; }
    const int bj = bi + t;
    const int row0 = bi * BM;
    const int col0 = bj * BN;
    const bool isdiag = (bi == bj);

    const signed char* A1g = g_q1 + (size_t)row0 * DDIM;
    const signed char* A2g = g_q2 + (size_t)row0 * DDIM;
    const signed char* B1g = g_q1 + (size_t)col0 * DDIM;
    const signed char* B2g = g_q2 + (size_t)col0 * DDIM;

    // warp tile: 32 (M) x 64 (N)
    const int wm = wid & 3, wn = wid >> 2;
    const int m0 = wm * 32, n0 = wn * 64;

    int acc1[2][8][4];   // q1*q1
    int acc2[2][8][4];   // q1*q2 + q2*q1
    #pragma unroll
    for (int i = 0; i < 2; i++)
        #pragma unroll
        for (int j = 0; j < 8; j++)
            #pragma unroll
            for (int q = 0; q < 4; q++) {
                acc1[i][j][q] = 0;
                acc2[i][j][q] = 0;
            }

    // shared lane-addressing for ldmatrix (A and B use the same pattern)
    const int lrow = (lane & 7) + ((lane >> 3) & 1) * 8;
    const int lcol = (lane >> 4) * 16;  // 16B block column within 32B k-step

    load_stage(smb, 0, A1g, A2g, B1g, B2g, 0, tid);
    CP_COMMIT();

    for (int it = 0; it < NCHUNK; it++) {
        if (it + 1 < NCHUNK) {
            load_stage(smb, (it + 1) & 1, A1g, A2g, B1g, B2g,
                       (it + 1) * BK, tid);
            CP_COMMIT();
            CP_WAIT1();
        } else {
            CP_WAIT0();
        }
        __syncthreads();

        const uint32_t A1 = smb + (it & 1) * STAGE_B;
        const uint32_t A2 = A1 + TILE_B;
        const uint32_t B1 = A2 + TILE_B;
        const uint32_t B2 = B1 + TILE_B;

        #pragma unroll
        for (int ks = 0; ks < 2; ks++) {
            const int kb = ks * 32;
            uint32_t a1r[2][4], a2r[2][4];
            #pragma unroll
            for (int mt = 0; mt < 2; mt++) {
                uint32_t off = (uint32_t)(m0 + mt * 16 + lrow) * TPADB
                             + kb + lcol;
                ldx4(a1r[mt], A1 + off);
                ldx4(a2r[mt], A2 + off);
            }
            uint32_t b1r[8][2], b2r[8][2];
            #pragma unroll
            for (int p = 0; p < 4; p++) {
                uint32_t off = (uint32_t)(n0 + p * 16 + lrow) * TPADB
                             + kb + lcol;
                uint32_t r1[4], r2[4];
                ldx4(r1, B1 + off);
                ldx4(r2, B2 + off);
                b1r[2 * p][0] = r1[0]; b1r[2 * p][1] = r1[2];
                b1r[2 * p + 1][0] = r1[1]; b1r[2 * p + 1][1] = r1[3];
                b2r[2 * p][0] = r2[0]; b2r[2 * p][1] = r2[2];
                b2r[2 * p + 1][0] = r2[1]; b2r[2 * p + 1][1] = r2[3];
            }
            // q1*q1 -> acc1 ; q1*q2 and q2*q1 -> acc2
            #pragma unroll
            for (int mt = 0; mt < 2; mt++)
                #pragma unroll
                for (int nt = 0; nt < 8; nt++)
                    imma16832(acc1[mt][nt], a1r[mt], b1r[nt]);
            #pragma unroll
            for (int mt = 0; mt < 2; mt++)
                #pragma unroll
                for (int nt = 0; nt < 8; nt++)
                    imma16832(acc2[mt][nt], a1r[mt], b2r[nt]);
            #pragma unroll
            for (int mt = 0; mt < 2; mt++)
                #pragma unroll
                for (int nt = 0; nt < 8; nt++)
                    imma16832(acc2[mt][nt], a2r[mt], b1r[nt]);
        }
        __syncthreads();
    }

    // ---------------- epilogue: dots -> smem dist tile ----------------
    float* ds = (float*)smem;
    const int g = lane >> 2;
    const int cl = (lane & 3) * 2;
    const float S1 = 1.0f / 256.0f;
    #pragma unroll
    for (int mt = 0; mt < 2; mt++) {
        const int rb = m0 + mt * 16 + g;
        #pragma unroll
        for (int nt = 0; nt < 8; nt++) {
            const int cb = n0 + nt * 8 + cl;
            #pragma unroll
            for (int q = 0; q < 4; q++) {
                int rr = rb + (q >> 1) * 8;
                int cc = cb + (q & 1);
                float dot = ((float)acc1[mt][nt][q]
                           + (float)acc2[mt][nt][q] * S1) * S1;
                ds[rr * DPAD + cc] = dot;
            }
        }
    }
    __syncthreads();

    const float INF = __int_as_float(0x7f800000);
    if (tid < 128) {
        // row pass: hardest positive + row min
        const int gi = row0 + tid;
        const float si = g_sq[gi];
        const int partner = (gi < NHALF) ? (gi + NHALF) : (gi - NHALF);
        float mn = INF;
        for (int c = 0; c < 128; c++) {
            const int gj = col0 + c;
            float dot = ds[tid * DPAD + c];
            float d2 = si + g_sq[gj] - 2.0f * dot;
            float dist = fmaxf(sqrtf(fmaxf(d2, 1e-14f)), 1e-7f);
            if (gj == partner) {
                g_pos[gi] = dist;
                g_pos[gj] = dist;
            } else if (gj != gi) {
                mn = fminf(mn, dist);
            }
        }
        atomicMin(&g_negmin_bits[gi], __float_as_uint(mn));
    } else if (!isdiag) {
        // col pass: col min (off-diagonal tiles only)
        const int c = tid - 128;
        const int gj = col0 + c;
        const float sj = g_sq[gj];
        const int partner = (gj < NHALF) ? (gj + NHALF) : (gj - NHALF);
        float mn = INF;
        for (int r = 0; r < 128; r++) {
            const int gi = row0 + r;
            float dot = ds[r * DPAD + c];
            float d2 = sj + g_sq[gi] - 2.0f * dot;
            float dist = fmaxf(sqrtf(fmaxf(d2, 1e-14f)), 1e-7f);
            if (gi != partner && gi != gj)
                mn = fminf(mn, dist);
        }
        atomicMin(&g_negmin_bits[gj], __float_as_uint(mn));
    }
}

// ---------------------------------------------------------------------------
// Kernel 3: finalize (single block)
// ---------------------------------------------------------------------------
__global__ void finalize_kernel(float* __restrict__ out) {
    const int t = threadIdx.x;  // 256 threads
    float sumdiff = 0.0f, sumrel = 0.0f, sumsq = 0.0f;
    int nrel = 0, good = 0;

    for (int r = t; r < NTOT; r += 256) {
        float pos = g_pos[r];
        float neg = __uint_as_float(g_negmin_bits[r]);
        float diff = pos - neg;
        float tl = fmaxf(diff + 0.1f, 0.0f);
        sumdiff += diff;
        if (tl > 1e-5f) { sumrel += tl; nrel++; }
        if (tl < 1e-5f) good++;
        sumsq += g_sq[r];
    }

    __shared__ float s_diff[256], s_rel[256], s_sq[256];
    __shared__ int   s_nrel[256], s_good[256];
    s_diff[t] = sumdiff; s_rel[t] = sumrel; s_sq[t] = sumsq;
    s_nrel[t] = nrel;    s_good[t] = good;
    __syncthreads();

    for (int stride = 128; stride > 0; stride >>= 1) {
        if (t < stride) {
            s_diff[t] += s_diff[t + stride];
            s_rel[t]  += s_rel[t + stride];
            s_sq[t]   += s_sq[t + stride];
            s_nrel[t] += s_nrel[t + stride];
            s_good[t] += s_good[t + stride];
        }
        __syncthreads();
    }

    if (t == 0) {
        int n_rel = s_nrel[0] > 0 ? s_nrel[0] : 1;
        out[0] = s_rel[0] / (float)n_rel;
        out[1] = s_diff[0] / (float)NTOT;
        out[2] = (float)s_good[0];
        out[3] = (float)(NTOT - s_good[0]);
        out[4] = sqrtf(s_sq[0] / (float)NTOT);
    }
}

// ---------------------------------------------------------------------------
extern "C" void kernel_launch(void* const* d_in, const int* in_sizes, int n_in,
                              void* d_out, int out_size) {
    const float* h1 = (const float*)d_in[0];
    const float* h2 = (const float*)d_in[1];
    float* out = (float*)d_out;

    cudaFuncSetAttribute(gemm_dist_kernel,
                         cudaFuncAttributeMaxDynamicSharedMemorySize, SM_TOTAL);

    prep_kernel<<<NTOT, 128>>>(h1, h2);
    gemm_dist_kernel<<<NBLK, 256, SM_TOTAL>>>();
    finalize_kernel<<<1, 256>>>(out);
}

// round 7
// speedup vs baseline: 2.1858x; 2.1858x over previous
#include <cuda_runtime.h>
#include <cuda_bf16.h>
#include <stdint.h>
#include <math.h>

#define NHALF 2048
#define NTOT  4096
#define DDIM  512

#define BM 128
#define BN 128
#define BK 32
#define NCHUNK (DDIM / BK)   // 16
#define NTILE 32
#define NBLK 528             // upper-triangle tiles

#define TPAD 40                      // bf16 elements per smem tile row (80 B)
#define TILE_B (128 * TPAD * 2)      // 10240 B per tile
#define STAGE_B (4 * TILE_B)         // Ah, Al, Bh, Bl
#define SM_TOTAL (2 * STAGE_B)       // 81920 B (dist tile overlays this)
#define DPAD 133                     // fp32 dist tile row stride

// ---------------- device globals ----------------
__device__ float          g_sq[NTOT];
__device__ unsigned       g_negmin_bits[NTOT];
__device__ float          g_pos[NTOT];
__device__ __nv_bfloat16  g_hi[NTOT * DDIM];
__device__ __nv_bfloat16  g_lo[NTOT * DDIM];

// ---------------- helpers ----------------
__device__ __forceinline__ uint32_t smem_u32(const void* p) {
    uint32_t a;
    asm("{ .reg .u64 t; cvta.to.shared.u64 t, %1; cvt.u32.u64 %0, t; }"
        : "=r"(a) : "l"(p));
    return a;
}
__device__ __forceinline__ void cp16(uint32_t dst, const void* src) {
    asm volatile("cp.async.cg.shared.global [%0], [%1], 16;"
                 :: "r"(dst), "l"(src));
}
#define CP_COMMIT() asm volatile("cp.async.commit_group;" ::: "memory")
#define CP_WAIT1()  asm volatile("cp.async.wait_group 1;" ::: "memory")
#define CP_WAIT0()  asm volatile("cp.async.wait_group 0;" ::: "memory")

__device__ __forceinline__ void ldx4(uint32_t* r, uint32_t addr) {
    asm volatile("ldmatrix.sync.aligned.m8n8.x4.shared.b16 {%0,%1,%2,%3}, [%4];"
                 : "=r"(r[0]), "=r"(r[1]), "=r"(r[2]), "=r"(r[3]) : "r"(addr));
}
__device__ __forceinline__ void mma16816(float* d, const uint32_t* a,
                                         const uint32_t* b) {
    asm volatile(
        "mma.sync.aligned.m16n8k16.row.col.f32.bf16.bf16.f32 "
        "{%0,%1,%2,%3}, {%4,%5,%6,%7}, {%8,%9}, {%0,%1,%2,%3};"
        : "+f"(d[0]), "+f"(d[1]), "+f"(d[2]), "+f"(d[3])
        : "r"(a[0]), "r"(a[1]), "r"(a[2]), "r"(a[3]), "r"(b[0]), "r"(b[1]));
}

// ---------------------------------------------------------------------------
// Kernel 1: row sums of squares + bf16 hi/lo split + scratch reset
// ---------------------------------------------------------------------------
__global__ void prep_kernel(const float* __restrict__ h1,
                            const float* __restrict__ h2) {
    int r = blockIdx.x;
    const float* src = (r < NHALF) ? (h1 + (size_t)r * DDIM)
                                   : (h2 + (size_t)(r - NHALF) * DDIM);
    int t = threadIdx.x;  // 0..127
    float4 v = ((const float4*)src)[t];
    float s = v.x * v.x + v.y * v.y + v.z * v.z + v.w * v.w;

    __nv_bfloat16 a0 = __float2bfloat16(v.x);
    __nv_bfloat16 a1 = __float2bfloat16(v.y);
    __nv_bfloat16 a2 = __float2bfloat16(v.z);
    __nv_bfloat16 a3 = __float2bfloat16(v.w);
    __nv_bfloat16 l0 = __float2bfloat16(v.x - __bfloat162float(a0));
    __nv_bfloat16 l1 = __float2bfloat16(v.y - __bfloat162float(a1));
    __nv_bfloat16 l2 = __float2bfloat16(v.z - __bfloat162float(a2));
    __nv_bfloat16 l3 = __float2bfloat16(v.w - __bfloat162float(a3));

    size_t base = (size_t)r * DDIM + 4 * t;
    __nv_bfloat162* gh = (__nv_bfloat162*)(g_hi + base);
    gh[0] = __nv_bfloat162(a0, a1);
    gh[1] = __nv_bfloat162(a2, a3);
    __nv_bfloat162* gl = (__nv_bfloat162*)(g_lo + base);
    gl[0] = __nv_bfloat162(l0, l1);
    gl[1] = __nv_bfloat162(l2, l3);

    #pragma unroll
    for (int off = 16; off > 0; off >>= 1)
        s += __shfl_xor_sync(0xffffffffu, s, off);

    __shared__ float warp_s[4];
    int lane = t & 31, wid = t >> 5;
    if (lane == 0) warp_s[wid] = s;
    __syncthreads();
    if (t == 0) {
        g_sq[r] = warp_s[0] + warp_s[1] + warp_s[2] + warp_s[3];
        g_negmin_bits[r] = 0x7f800000u;  // +inf
        g_pos[r] = 0.0f;
    }
}

// ---------------------------------------------------------------------------
// async-load one pipeline stage (4 tiles of 128 x 32 bf16)
// ---------------------------------------------------------------------------
__device__ __forceinline__ void load_stage(uint32_t smb, int stage,
                                           const __nv_bfloat16* ah,
                                           const __nv_bfloat16* al,
                                           const __nv_bfloat16* bh,
                                           const __nv_bfloat16* bl,
                                           int k0, int tid) {
    const __nv_bfloat16* srcs[4] = {ah, al, bh, bl};
    uint32_t base = smb + stage * STAGE_B;
    #pragma unroll
    for (int t = 0; t < 4; t++) {
        #pragma unroll
        for (int i = 0; i < 2; i++) {
            int chunk = tid * 2 + i;       // 0..511
            int r = chunk >> 2;            // 0..127
            int c = chunk & 3;             // 16B chunk within 64B row
            cp16(base + t * TILE_B + r * (TPAD * 2) + c * 16,
                 srcs[t] + (size_t)r * DDIM + k0 + c * 8);
        }
    }
}

// ---------------------------------------------------------------------------
// Kernel 2: bf16x3 mma.sync X*X^T (upper triangle) + fused distance epilogue
// ---------------------------------------------------------------------------
__global__ __launch_bounds__(256, 2)
void gemm_dist_kernel() {
    extern __shared__ char smem[];
    const uint32_t smb = smem_u32(smem);
    const int tid = threadIdx.x;
    const int wid = tid >> 5, lane = tid & 31;

    // decode upper-triangle tile index
    int t = blockIdx.x;
    int bi = 0;
    while (t >= NTILE - bi) { t -= NTILE - bi; bi++; }
    const int bj = bi + t;
    const int row0 = bi * BM;
    const int col0 = bj * BN;
    const bool isdiag = (bi == bj);

    const __nv_bfloat16* Ah_g = g_hi + (size_t)row0 * DDIM;
    const __nv_bfloat16* Al_g = g_lo + (size_t)row0 * DDIM;
    const __nv_bfloat16* Bh_g = g_hi + (size_t)col0 * DDIM;
    const __nv_bfloat16* Bl_g = g_lo + (size_t)col0 * DDIM;

    // warp tile: 32 (M) x 64 (N)
    const int wm = wid & 3, wn = wid >> 2;
    const int m0 = wm * 32, n0 = wn * 64;

    float acc[2][8][4];
    #pragma unroll
    for (int i = 0; i < 2; i++)
        #pragma unroll
        for (int j = 0; j < 8; j++)
            #pragma unroll
            for (int q = 0; q < 4; q++)
                acc[i][j][q] = 0.0f;

    // ldmatrix lane addressing
    const int arow = (lane & 7) + ((lane >> 3) & 1) * 8;  // + mtile row base
    const int acol = (lane >> 4) * 8;                     // + k base
    const int brow = (lane & 7) + ((lane >> 4) << 3);     // + ntile-pair base
    const int bcol = ((lane >> 3) & 1) * 8;               // + k base

    load_stage(smb, 0, Ah_g, Al_g, Bh_g, Bl_g, 0, tid);
    CP_COMMIT();

    for (int it = 0; it < NCHUNK; it++) {
        if (it + 1 < NCHUNK) {
            load_stage(smb, (it + 1) & 1, Ah_g, Al_g, Bh_g, Bl_g,
                       (it + 1) * BK, tid);
            CP_COMMIT();
            CP_WAIT1();
        } else {
            CP_WAIT0();
        }
        __syncthreads();

        const uint32_t Ah = smb + (it & 1) * STAGE_B;
        const uint32_t Al = Ah + TILE_B;
        const uint32_t Bh = Al + TILE_B;
        const uint32_t Bl = Bh + TILE_B;

        #pragma unroll
        for (int ks = 0; ks < 2; ks++) {
            const int kb = ks * 16;
            uint32_t ahr[2][4], alr[2][4];
            #pragma unroll
            for (int mt = 0; mt < 2; mt++) {
                uint32_t off = (uint32_t)(m0 + mt * 16 + arow) * (TPAD * 2)
                             + (kb + acol) * 2;
                ldx4(ahr[mt], Ah + off);
                ldx4(alr[mt], Al + off);
            }
            // stream B per 16-col group to keep register pressure low
            #pragma unroll
            for (int p = 0; p < 4; p++) {
                uint32_t off = (uint32_t)(n0 + p * 16 + brow) * (TPAD * 2)
                             + (kb + bcol) * 2;
                uint32_t rh[4], rl[4];
                ldx4(rh, Bh + off);
                ldx4(rl, Bl + off);
                uint32_t b0h[2] = {rh[0], rh[1]}, b1h[2] = {rh[2], rh[3]};
                uint32_t b0l[2] = {rl[0], rl[1]}, b1l[2] = {rl[2], rl[3]};
                #pragma unroll
                for (int mt = 0; mt < 2; mt++) {
                    mma16816(acc[mt][2 * p],     ahr[mt], b0h);
                    mma16816(acc[mt][2 * p + 1], ahr[mt], b1h);
                    mma16816(acc[mt][2 * p],     ahr[mt], b0l);
                    mma16816(acc[mt][2 * p + 1], ahr[mt], b1l);
                    mma16816(acc[mt][2 * p],     alr[mt], b0h);
                    mma16816(acc[mt][2 * p + 1], alr[mt], b1h);
                }
            }
        }
        __syncthreads();
    }

    // ---------------- epilogue: dump dots to smem dist tile ----------------
    float* ds = (float*)smem;
    const int g = lane >> 2;
    const int cl = (lane & 3) * 2;
    #pragma unroll
    for (int mt = 0; mt < 2; mt++) {
        const int rb = m0 + mt * 16 + g;
        #pragma unroll
        for (int nt = 0; nt < 8; nt++) {
            const int cb = n0 + nt * 8 + cl;
            ds[rb * DPAD + cb]           = acc[mt][nt][0];
            ds[rb * DPAD + cb + 1]       = acc[mt][nt][1];
            ds[(rb + 8) * DPAD + cb]     = acc[mt][nt][2];
            ds[(rb + 8) * DPAD + cb + 1] = acc[mt][nt][3];
        }
    }
    __syncthreads();

    const float INF = __int_as_float(0x7f800000);
    if (tid < 128) {
        // row pass: hardest positive + row min
        const int gi = row0 + tid;
        const float si = g_sq[gi];
        const int partner = (gi < NHALF) ? (gi + NHALF) : (gi - NHALF);
        float mn = INF;
        for (int c = 0; c < 128; c++) {
            const int gj = col0 + c;
            float dot = ds[tid * DPAD + c];
            float d2 = si + g_sq[gj] - 2.0f * dot;
            float dist = fmaxf(sqrtf(fmaxf(d2, 1e-14f)), 1e-7f);
            if (gj == partner) {
                g_pos[gi] = dist;
                g_pos[gj] = dist;
            } else if (gj != gi) {
                mn = fminf(mn, dist);
            }
        }
        atomicMin(&g_negmin_bits[gi], __float_as_uint(mn));
    } else if (!isdiag) {
        // col pass: col min (off-diagonal tiles only)
        const int c = tid - 128;
        const int gj = col0 + c;
        const float sj = g_sq[gj];
        const int partner = (gj < NHALF) ? (gj + NHALF) : (gj - NHALF);
        float mn = INF;
        for (int r = 0; r < 128; r++) {
            const int gi = row0 + r;
            float dot = ds[r * DPAD + c];
            float d2 = sj + g_sq[gi] - 2.0f * dot;
            float dist = fmaxf(sqrtf(fmaxf(d2, 1e-14f)), 1e-7f);
            if (gi != partner && gi != gj)
                mn = fminf(mn, dist);
        }
        atomicMin(&g_negmin_bits[gj], __float_as_uint(mn));
    }
}

// ---------------------------------------------------------------------------
// Kernel 3: finalize (single block)
// ---------------------------------------------------------------------------
__global__ void finalize_kernel(float* __restrict__ out) {
    const int t = threadIdx.x;  // 256 threads
    float sumdiff = 0.0f, sumrel = 0.0f, sumsq = 0.0f;
    int nrel = 0, good = 0;

    for (int r = t; r < NTOT; r += 256) {
        float pos = g_pos[r];
        float neg = __uint_as_float(g_negmin_bits[r]);
        float diff = pos - neg;
        float tl = fmaxf(diff + 0.1f, 0.0f);
        sumdiff += diff;
        if (tl > 1e-5f) { sumrel += tl; nrel++; }
        if (tl < 1e-5f) good++;
        sumsq += g_sq[r];
    }

    __shared__ float s_diff[256], s_rel[256], s_sq[256];
    __shared__ int   s_nrel[256], s_good[256];
    s_diff[t] = sumdiff; s_rel[t] = sumrel; s_sq[t] = sumsq;
    s_nrel[t] = nrel;    s_good[t] = good;
    __syncthreads();

    for (int stride = 128; stride > 0; stride >>= 1) {
        if (t < stride) {
            s_diff[t] += s_diff[t + stride];
            s_rel[t]  += s_rel[t + stride];
            s_sq[t]   += s_sq[t + stride];
            s_nrel[t] += s_nrel[t + stride];
            s_good[t] += s_good[t + stride];
        }
        __syncthreads();
    }

    if (t == 0) {
        int n_rel = s_nrel[0] > 0 ? s_nrel[0] : 1;
        out[0] = s_rel[0] / (float)n_rel;
        out[1] = s_diff[0] / (float)NTOT;
        out[2] = (float)s_good[0];
        out[3] = (float)(NTOT - s_good[0]);
        out[4] = sqrtf(s_sq[0] / (float)NTOT);
    }
}

// ---------------------------------------------------------------------------
extern "C" void kernel_launch(void* const* d_in, const int* in_sizes, int n_in,
                              void* d_out, int out_size) {
    const float* h1 = (const float*)d_in[0];
    const float* h2 = (const float*)d_in[1];
    float* out = (float*)d_out;

    cudaFuncSetAttribute(gemm_dist_kernel,
                         cudaFuncAttributeMaxDynamicSharedMemorySize, SM_TOTAL);

    prep_kernel<<<NTOT, 128>>>(h1, h2);
    gemm_dist_kernel<<<NBLK, 256, SM_TOTAL>>>();
    finalize_kernel<<<1, 256>>>(out);
}